// round 2
// baseline (speedup 1.0000x reference)
#include <cuda_runtime.h>
#include <math.h>

// Problem constants
#define BB      2
#define SS      2048
#define DM      1024
#define NH      16
#define DKH     64
#define STRIDE  32
#define NSTR    64          // SS / STRIDE
#define MROWS   (BB*SS)     // 4096

// Scratch (allocation-free rule: __device__ globals)
__device__ float g_q[(size_t)MROWS * DM];
__device__ float g_k[(size_t)MROWS * DM];
__device__ float g_v[(size_t)MROWS * DM];
__device__ float g_ctx[(size_t)MROWS * DM];

// ---------------------------------------------------------------------------
// Warp reductions
// ---------------------------------------------------------------------------
__device__ __forceinline__ float wsum(float v) {
    #pragma unroll
    for (int o = 16; o > 0; o >>= 1) v += __shfl_xor_sync(0xffffffffu, v, o);
    return v;
}
__device__ __forceinline__ float wmax(float v) {
    #pragma unroll
    for (int o = 16; o > 0; o >>= 1) v = fmaxf(v, __shfl_xor_sync(0xffffffffu, v, o));
    return v;
}

// ---------------------------------------------------------------------------
// C[M=4096, N=1024] = A[M, K=1024] @ W[K, N] + bias[N]
// 128x128 block tile, BK=8, 256 threads, 8x8 per-thread microtile.
// ---------------------------------------------------------------------------
__global__ __launch_bounds__(256) void gemm_bias(
    const float* __restrict__ A, const float* __restrict__ W,
    const float* __restrict__ bias, float* __restrict__ C)
{
    __shared__ __align__(16) float As[8][128];
    __shared__ __align__(16) float Wsm[8][128];

    const int tid  = threadIdx.x;
    const int row0 = blockIdx.y * 128;
    const int col0 = blockIdx.x * 128;

    const int arow = tid >> 1, acol = (tid & 1) << 2;   // A tile: 128x8
    const int wrow = tid >> 5, wcol = (tid & 31) << 2;  // W tile: 8x128
    const int tx = tid & 15, ty = tid >> 4;

    float acc[8][8];
    #pragma unroll
    for (int i = 0; i < 8; i++)
        #pragma unroll
        for (int j = 0; j < 8; j++) acc[i][j] = 0.f;

    const float* Aptr = A + (size_t)(row0 + arow) * DM + acol;
    const float* Wptr = W + (size_t)wrow * DM + col0 + wcol;

    for (int k0 = 0; k0 < DM; k0 += 8) {
        float4 a4 = *(const float4*)(Aptr + k0);
        float4 w4 = *(const float4*)(Wptr + (size_t)k0 * DM);
        As[acol + 0][arow] = a4.x;
        As[acol + 1][arow] = a4.y;
        As[acol + 2][arow] = a4.z;
        As[acol + 3][arow] = a4.w;
        *(float4*)&Wsm[wrow][wcol] = w4;
        __syncthreads();

        #pragma unroll
        for (int kk = 0; kk < 8; kk++) {
            float af[8], wf[8];
            *(float4*)(af + 0) = *(const float4*)&As[kk][ty * 4];
            *(float4*)(af + 4) = *(const float4*)&As[kk][ty * 4 + 64];
            *(float4*)(wf + 0) = *(const float4*)&Wsm[kk][tx * 4];
            *(float4*)(wf + 4) = *(const float4*)&Wsm[kk][tx * 4 + 64];
            #pragma unroll
            for (int i = 0; i < 8; i++)
                #pragma unroll
                for (int j = 0; j < 8; j++)
                    acc[i][j] += af[i] * wf[j];
        }
        __syncthreads();
    }

    #pragma unroll
    for (int ii = 0; ii < 2; ii++)
        #pragma unroll
        for (int i = 0; i < 4; i++) {
            const int r = row0 + ty * 4 + ii * 64 + i;
            #pragma unroll
            for (int jj = 0; jj < 2; jj++) {
                const int c = col0 + tx * 4 + jj * 64;
                float4 b4 = *(const float4*)&bias[c];
                float4 o;
                o.x = acc[ii * 4 + i][jj * 4 + 0] + b4.x;
                o.y = acc[ii * 4 + i][jj * 4 + 1] + b4.y;
                o.z = acc[ii * 4 + i][jj * 4 + 2] + b4.z;
                o.w = acc[ii * 4 + i][jj * 4 + 3] + b4.w;
                *(float4*)&C[(size_t)r * DM + c] = o;
            }
        }
}

// ---------------------------------------------------------------------------
// Regular rows (i % 32 != 0): keys = {j%32==0, j<=i} (<=64) + diagonal.
// One block per (b,h, 64-row chunk). Strided K/V rows cached in smem.
// One warp per query; lane-per-key scores, lane-per-dim context.
// ---------------------------------------------------------------------------
__global__ __launch_bounds__(256) void attn_regular(
    const float* __restrict__ q, const float* __restrict__ k,
    const float* __restrict__ v, float* __restrict__ ctx)
{
    __shared__ float Ks[NSTR * 65];
    __shared__ float Vs[NSTR * 65];
    __shared__ float Qs[8][64];
    __shared__ float Ps[8][64];

    const int bh = blockIdx.x;           // 0..31
    const int b = bh >> 4, h = bh & 15;
    const int tid = threadIdx.x, warp = tid >> 5, lane = tid & 31;
    const size_t base = (size_t)b * SS * DM + (size_t)h * DKH;

    const float* kb = k + base;
    const float* vb = v + base;

    // Cache the 64 strided K/V rows (64 floats each) in smem
    for (int idx = tid; idx < NSTR * DKH; idx += 256) {
        const int t = idx >> 6, d = idx & 63;
        const size_t off = (size_t)(t * STRIDE) * DM + d;
        Ks[t * 65 + d] = kb[off];
        Vs[t * 65 + d] = vb[off];
    }
    __syncthreads();

    const int irow0 = blockIdx.y * 64 + warp * 8;
    for (int qi = 0; qi < 8; qi++) {
        const int i = irow0 + qi;
        if ((i & (STRIDE - 1)) == 0) continue;  // handled by attn_special

        const float* qrow = q + base + (size_t)i * DM;
        Qs[warp][lane]      = qrow[lane];
        Qs[warp][lane + 32] = qrow[lane + 32];
        __syncwarp();

        const int nst = i / STRIDE + 1;  // strided keys j=32t, t<nst (all < i)

        // Diagonal score (k_i from global, warp-distributed dot)
        const float* krow = kb + (size_t)i * DM;
        const int d0 = 2 * lane;
        float dp = Qs[warp][d0] * krow[d0] + Qs[warp][d0 + 1] * krow[d0 + 1];
        const float sdiag = wsum(dp) * 0.125f;

        // Strided scores: lane handles keys t=lane and t=lane+32
        float s0 = 0.f, s1 = 0.f;
        #pragma unroll 8
        for (int d = 0; d < DKH; d++) {
            const float qd = Qs[warp][d];
            s0 += qd * Ks[lane * 65 + d];
            s1 += qd * Ks[(lane + 32) * 65 + d];
        }
        s0 = (lane      < nst) ? s0 * 0.125f : -1e30f;
        s1 = (lane + 32 < nst) ? s1 * 0.125f : -1e30f;

        const float m = wmax(fmaxf(fmaxf(s0, s1), sdiag));
        const float e0 = (lane      < nst) ? __expf(s0 - m) : 0.f;
        const float e1 = (lane + 32 < nst) ? __expf(s1 - m) : 0.f;
        const float ediag = __expf(sdiag - m);
        const float den = wsum(e0 + e1) + ediag;

        Ps[warp][lane]      = e0;
        Ps[warp][lane + 32] = e1;
        __syncwarp();

        // Context: lane owns dims d0, d0+1
        const float* vrow = vb + (size_t)i * DM;
        float a0 = ediag * vrow[d0];
        float a1 = ediag * vrow[d0 + 1];
        #pragma unroll 8
        for (int t = 0; t < NSTR; t++) {
            const float p = Ps[warp][t];   // zero beyond nst
            a0 += p * Vs[t * 65 + d0];
            a1 += p * Vs[t * 65 + d0 + 1];
        }
        const float inv = 1.0f / den;
        float* out = ctx + base + (size_t)i * DM;
        out[d0]     = a0 * inv;
        out[d0 + 1] = a1 * inv;
        __syncwarp();
    }
}

// ---------------------------------------------------------------------------
// Special rows (i = 32m): keys = {j%32==0, j<i} U {j>=i}.
// One warp per query, online softmax stream. K/V slices per (b,h) are 256B
// contiguous -> coalesced float2 loads, L2-resident.
// ---------------------------------------------------------------------------
__global__ __launch_bounds__(256) void attn_special(
    const float* __restrict__ q, const float* __restrict__ k,
    const float* __restrict__ v, float* __restrict__ ctx)
{
    const int bh = blockIdx.x;
    const int b = bh >> 4, h = bh & 15;
    const int warp = threadIdx.x >> 5, lane = threadIdx.x & 31;
    const int m = blockIdx.y * 8 + warp;   // 0..63
    const int i = m * STRIDE;
    const size_t base = (size_t)b * SS * DM + (size_t)h * DKH;

    const int d0 = 2 * lane;
    const float* qrow = q + base + (size_t)i * DM;
    const float q0 = qrow[d0], q1 = qrow[d0 + 1];
    const float* kb = k + base;
    const float* vb = v + base;

    float mx = -1e30f, den = 0.f, a0 = 0.f, a1 = 0.f;

    auto process = [&](int j) {
        const float2 kk = *(const float2*)(kb + (size_t)j * DM + d0);
        const float2 vv = *(const float2*)(vb + (size_t)j * DM + d0);
        float p = q0 * kk.x + q1 * kk.y;
        const float s = wsum(p) * 0.125f;
        const float mn = fmaxf(mx, s);
        const float c = __expf(mx - mn);
        const float e = __expf(s - mn);
        den = den * c + e;
        a0 = a0 * c + e * vv.x;
        a1 = a1 * c + e * vv.y;
        mx = mn;
    };

    for (int t = 0; t < m; t++) process(t * STRIDE);  // strided prefix
    for (int j = i; j < SS; j++) process(j);          // dense suffix

    const float inv = 1.0f / den;
    float* out = ctx + base + (size_t)i * DM;
    out[d0]     = a0 * inv;
    out[d0 + 1] = a1 * inv;
}

// ---------------------------------------------------------------------------
extern "C" void kernel_launch(void* const* d_in, const int* in_sizes, int n_in,
                              void* d_out, int out_size)
{
    const float* q_in = (const float*)d_in[0];
    const float* k_in = (const float*)d_in[1];
    const float* v_in = (const float*)d_in[2];
    const float* Wq = (const float*)d_in[3];
    const float* bq = (const float*)d_in[4];
    const float* Wk = (const float*)d_in[5];
    const float* bk = (const float*)d_in[6];
    const float* Wv = (const float*)d_in[7];
    const float* bv = (const float*)d_in[8];
    const float* Wo = (const float*)d_in[9];
    const float* bo = (const float*)d_in[10];

    float *pq, *pk, *pv, *pc;
    cudaGetSymbolAddress((void**)&pq, g_q);
    cudaGetSymbolAddress((void**)&pk, g_k);
    cudaGetSymbolAddress((void**)&pv, g_v);
    cudaGetSymbolAddress((void**)&pc, g_ctx);

    const dim3 gg(DM / 128, MROWS / 128);   // (8, 32)

    gemm_bias<<<gg, 256>>>(q_in, Wq, bq, pq);
    gemm_bias<<<gg, 256>>>(k_in, Wk, bk, pk);
    gemm_bias<<<gg, 256>>>(v_in, Wv, bv, pv);

    attn_regular<<<dim3(BB * NH, SS / 64), 256>>>(pq, pk, pv, pc);
    attn_special<<<dim3(BB * NH, NSTR / 8), 256>>>(pq, pk, pv, pc);

    gemm_bias<<<gg, 256>>>(pc, Wo, bo, (float*)d_out);
}

// round 6
// speedup vs baseline: 1.3719x; 1.3719x over previous
#include <cuda_runtime.h>
#include <cuda_bf16.h>
#include <math.h>
#include <stdint.h>

// Problem constants
#define BB      2
#define SS      2048
#define DM      1024
#define NH      16
#define DKH     64
#define STRIDE  32
#define NSTR    64          // SS / STRIDE
#define MROWS   (BB*SS)     // 4096

// ---------------------------------------------------------------------------
// Scratch (allocation-free rule: __device__ globals)
// ---------------------------------------------------------------------------
__device__ float g_q[(size_t)MROWS * DM];
__device__ float g_k[(size_t)MROWS * DM];
__device__ float g_v[(size_t)MROWS * DM];
__device__ float g_ctx[(size_t)MROWS * DM];
__device__ __nv_bfloat16 g_ahi[(size_t)MROWS * DM];
__device__ __nv_bfloat16 g_alo[(size_t)MROWS * DM];
__device__ __nv_bfloat16 g_wthi[(size_t)4 * DM * DM];
__device__ __nv_bfloat16 g_wtlo[(size_t)4 * DM * DM];

// ---------------------------------------------------------------------------
// Helpers
// ---------------------------------------------------------------------------
__device__ __forceinline__ uint32_t smem_u32(const void* p) {
    uint32_t a;
    asm("{ .reg .u64 t; cvta.to.shared.u64 t, %1; cvt.u32.u64 %0, t; }" : "=r"(a) : "l"(p));
    return a;
}

#define CP16(dst, src) \
    asm volatile("cp.async.cg.shared.global [%0], [%1], 16;" :: "r"(dst), "l"(src))

#define LDSM4(r, addr) \
    asm volatile("ldmatrix.sync.aligned.m8n8.x4.shared.b16 {%0,%1,%2,%3}, [%4];" \
        : "=r"((r)[0]), "=r"((r)[1]), "=r"((r)[2]), "=r"((r)[3]) : "r"(addr))

#define MMA16816(c, a, b) \
    asm volatile("mma.sync.aligned.m16n8k16.row.col.f32.bf16.bf16.f32 " \
        "{%0,%1,%2,%3}, {%4,%5,%6,%7}, {%8,%9}, {%0,%1,%2,%3};" \
        : "+f"((c)[0]), "+f"((c)[1]), "+f"((c)[2]), "+f"((c)[3]) \
        : "r"((a)[0]), "r"((a)[1]), "r"((a)[2]), "r"((a)[3]), "r"((b)[0]), "r"((b)[1]))

// ---------------------------------------------------------------------------
// Elementwise fp32 -> bf16 hi/lo split
// ---------------------------------------------------------------------------
__global__ __launch_bounds__(256) void convert_act(
    const float* __restrict__ x, __nv_bfloat16* __restrict__ hi,
    __nv_bfloat16* __restrict__ lo, int n)
{
    int i = (blockIdx.x * 256 + threadIdx.x) * 4;
    if (i >= n) return;
    float4 v = *(const float4*)(x + i);
    __nv_bfloat16 h0 = __float2bfloat16(v.x), h1 = __float2bfloat16(v.y);
    __nv_bfloat16 h2 = __float2bfloat16(v.z), h3 = __float2bfloat16(v.w);
    __nv_bfloat16 l0 = __float2bfloat16(v.x - __bfloat162float(h0));
    __nv_bfloat16 l1 = __float2bfloat16(v.y - __bfloat162float(h1));
    __nv_bfloat16 l2 = __float2bfloat16(v.z - __bfloat162float(h2));
    __nv_bfloat16 l3 = __float2bfloat16(v.w - __bfloat162float(h3));
    __nv_bfloat162 ph0 = {h0, h1}, ph1 = {h2, h3}, pl0 = {l0, l1}, pl1 = {l2, l3};
    *(__nv_bfloat162*)(hi + i)     = ph0;
    *(__nv_bfloat162*)(hi + i + 2) = ph1;
    *(__nv_bfloat162*)(lo + i)     = pl0;
    *(__nv_bfloat162*)(lo + i + 2) = pl1;
}

// ---------------------------------------------------------------------------
// Transpose + convert: W[K=1024][N=1024] fp32 -> Wt_hi/Wt_lo [N][K] bf16
// ---------------------------------------------------------------------------
__global__ __launch_bounds__(256) void wtrans(
    const float* __restrict__ W, __nv_bfloat16* __restrict__ Thi,
    __nv_bfloat16* __restrict__ Tlo)
{
    __shared__ float tile[32][33];
    const int tx = threadIdx.x & 31, ty = threadIdx.x >> 5;
    const int n0 = blockIdx.x * 32, k0 = blockIdx.y * 32;
    #pragma unroll
    for (int i = 0; i < 32; i += 8)
        tile[ty + i][tx] = W[(size_t)(k0 + ty + i) * DM + n0 + tx];
    __syncthreads();
    #pragma unroll
    for (int i = 0; i < 32; i += 8) {
        float x = tile[tx][ty + i];
        __nv_bfloat16 h = __float2bfloat16(x);
        __nv_bfloat16 l = __float2bfloat16(x - __bfloat162float(h));
        Thi[(size_t)(n0 + ty + i) * DM + k0 + tx] = h;
        Tlo[(size_t)(n0 + ty + i) * DM + k0 + tx] = l;
    }
}

// ---------------------------------------------------------------------------
// mma.sync bf16 GEMM: C[4096,1024] = A @ Wt^T + bias, hi/lo 3-term split.
// 128x128 CTA tile, BK=64, 2-stage cp.async double buffer, SW128 swizzle.
// 8 warps in 2(M)x4(N), warp tile 64x32, mma m16n8k16.
// SMEM per stage (64KB): Ah(16K) Al(16K) Bh(16K) Bl(16K); 2 stages = 128KB.
// ---------------------------------------------------------------------------
#define TILE_B   16384
#define STAGE_B  65536
#define GEMM_SMEM (2 * STAGE_B)
#define NKB      (DM / 64)   // 16

__global__ __launch_bounds__(256, 1) void gemm_mma(
    const __nv_bfloat16* __restrict__ Ahi, const __nv_bfloat16* __restrict__ Alo,
    const __nv_bfloat16* __restrict__ Bhi, const __nv_bfloat16* __restrict__ Blo,
    const float* __restrict__ bias, float* __restrict__ C)
{
    extern __shared__ __align__(1024) char smem[];
    const uint32_t sbase = smem_u32(smem);
    const int tid = threadIdx.x, wid = tid >> 5, lane = tid & 31;
    const int n0 = blockIdx.x * 128;
    const int m0 = blockIdx.y * 128;
    const int wm = wid >> 2, wn = wid & 3;     // warp tile: rows 64*wm, cols 32*wn

    // Loader: thread t -> row t/2 (0..127), chunks (t&1)*4 .. +3 (16B each)
    const int lr = tid >> 1;
    const int lc = (tid & 1) * 4;
    const __nv_bfloat16* gAh = Ahi + (size_t)(m0 + lr) * DM;
    const __nv_bfloat16* gAl = Alo + (size_t)(m0 + lr) * DM;
    const __nv_bfloat16* gBh = Bhi + (size_t)(n0 + lr) * DM;
    const __nv_bfloat16* gBl = Blo + (size_t)(n0 + lr) * DM;

    auto load_stage = [&](int s, int kb) {
        const int k0 = kb * 64;
        const uint32_t sdst = sbase + s * STAGE_B;
        #pragma unroll
        for (int j = 0; j < 4; j++) {
            const int chunk = lc + j;
            const uint32_t off = (uint32_t)(lr * 128 + chunk * 16);
            const uint32_t sw = off ^ ((off >> 3) & 0x70);
            CP16(sdst + 0 * TILE_B + sw, gAh + k0 + chunk * 8);
            CP16(sdst + 1 * TILE_B + sw, gAl + k0 + chunk * 8);
            CP16(sdst + 2 * TILE_B + sw, gBh + k0 + chunk * 8);
            CP16(sdst + 3 * TILE_B + sw, gBl + k0 + chunk * 8);
        }
        asm volatile("cp.async.commit_group;" ::: "memory");
    };

    float acc[4][4][4];
    #pragma unroll
    for (int mt = 0; mt < 4; mt++)
        #pragma unroll
        for (int nt = 0; nt < 4; nt++)
            #pragma unroll
            for (int i = 0; i < 4; i++) acc[mt][nt][i] = 0.f;

    load_stage(0, 0);
    load_stage(1, 1);

    const int la = lane & 15;            // row within 16-row ldmatrix tile
    const int hb = (lane >> 4) * 16;     // byte offset selecting k-half (0 / 8 elems)

    for (int kb = 0; kb < NKB; kb++) {
        if (kb < NKB - 1) asm volatile("cp.async.wait_group 1;" ::: "memory");
        else              asm volatile("cp.async.wait_group 0;" ::: "memory");
        __syncthreads();

        const uint32_t sa = sbase + (kb & 1) * STAGE_B;
        #pragma unroll
        for (int kk = 0; kk < 4; kk++) {
            uint32_t ah[4][4], al[4][4], bh[4][2], bl[4][2];
            #pragma unroll
            for (int mt = 0; mt < 4; mt++) {
                const uint32_t off = (uint32_t)((64 * wm + 16 * mt + la) * 128 + 32 * kk + hb);
                const uint32_t sw = off ^ ((off >> 3) & 0x70);
                LDSM4(ah[mt], sa + 0 * TILE_B + sw);
                LDSM4(al[mt], sa + 1 * TILE_B + sw);
            }
            #pragma unroll
            for (int bp = 0; bp < 2; bp++) {
                const uint32_t off = (uint32_t)((32 * wn + 16 * bp + la) * 128 + 32 * kk + hb);
                const uint32_t sw = off ^ ((off >> 3) & 0x70);
                uint32_t t[4];
                LDSM4(t, sa + 2 * TILE_B + sw);
                bh[2 * bp][0] = t[0]; bh[2 * bp + 1][0] = t[1];
                bh[2 * bp][1] = t[2]; bh[2 * bp + 1][1] = t[3];
                LDSM4(t, sa + 3 * TILE_B + sw);
                bl[2 * bp][0] = t[0]; bl[2 * bp + 1][0] = t[1];
                bl[2 * bp][1] = t[2]; bl[2 * bp + 1][1] = t[3];
            }
            #pragma unroll
            for (int mt = 0; mt < 4; mt++)
                #pragma unroll
                for (int nt = 0; nt < 4; nt++) {
                    MMA16816(acc[mt][nt], ah[mt], bh[nt]);
                    MMA16816(acc[mt][nt], ah[mt], bl[nt]);
                    MMA16816(acc[mt][nt], al[mt], bh[nt]);
                }
        }
        __syncthreads();
        if (kb + 2 < NKB) load_stage(kb & 1, kb + 2);
    }

    // Epilogue: D frag mapping: d0,d1 -> (row l/4, col 2(l&3)); d2,d3 -> row+8
    const int er = lane >> 2, ec = (lane & 3) * 2;
    #pragma unroll
    for (int mt = 0; mt < 4; mt++) {
        const int row = m0 + 64 * wm + 16 * mt + er;
        #pragma unroll
        for (int nt = 0; nt < 4; nt++) {
            const int col = n0 + 32 * wn + 8 * nt + ec;
            const float2 b2 = *(const float2*)(bias + col);
            float2 o0, o1;
            o0.x = acc[mt][nt][0] + b2.x; o0.y = acc[mt][nt][1] + b2.y;
            o1.x = acc[mt][nt][2] + b2.x; o1.y = acc[mt][nt][3] + b2.y;
            *(float2*)(C + (size_t)row * DM + col) = o0;
            *(float2*)(C + (size_t)(row + 8) * DM + col) = o1;
        }
    }
}

// ---------------------------------------------------------------------------
// Warp reductions
// ---------------------------------------------------------------------------
__device__ __forceinline__ float wsum(float v) {
    #pragma unroll
    for (int o = 16; o > 0; o >>= 1) v += __shfl_xor_sync(0xffffffffu, v, o);
    return v;
}
__device__ __forceinline__ float wmax(float v) {
    #pragma unroll
    for (int o = 16; o > 0; o >>= 1) v = fmaxf(v, __shfl_xor_sync(0xffffffffu, v, o));
    return v;
}

// ---------------------------------------------------------------------------
// Regular rows (i % 32 != 0): keys = {j%32==0, j<=i} (<=64) + diagonal.
// ---------------------------------------------------------------------------
__global__ __launch_bounds__(256) void attn_regular(
    const float* __restrict__ q, const float* __restrict__ k,
    const float* __restrict__ v, float* __restrict__ ctx)
{
    __shared__ float Ks[NSTR * 65];
    __shared__ float Vs[NSTR * 65];
    __shared__ float Qs[8][64];
    __shared__ float Ps[8][64];

    const int bh = blockIdx.x;
    const int b = bh >> 4, h = bh & 15;
    const int tid = threadIdx.x, warp = tid >> 5, lane = tid & 31;
    const size_t base = (size_t)b * SS * DM + (size_t)h * DKH;

    const float* kb = k + base;
    const float* vb = v + base;

    for (int idx = tid; idx < NSTR * DKH; idx += 256) {
        const int t = idx >> 6, d = idx & 63;
        const size_t off = (size_t)(t * STRIDE) * DM + d;
        Ks[t * 65 + d] = kb[off];
        Vs[t * 65 + d] = vb[off];
    }
    __syncthreads();

    const int irow0 = blockIdx.y * 64 + warp * 8;
    for (int qi = 0; qi < 8; qi++) {
        const int i = irow0 + qi;
        if ((i & (STRIDE - 1)) == 0) continue;

        const float* qrow = q + base + (size_t)i * DM;
        Qs[warp][lane]      = qrow[lane];
        Qs[warp][lane + 32] = qrow[lane + 32];
        __syncwarp();

        const int nst = i / STRIDE + 1;

        const float* krow = kb + (size_t)i * DM;
        const int d0 = 2 * lane;
        float dp = Qs[warp][d0] * krow[d0] + Qs[warp][d0 + 1] * krow[d0 + 1];
        const float sdiag = wsum(dp) * 0.125f;

        float s0 = 0.f, s1 = 0.f;
        #pragma unroll 8
        for (int d = 0; d < DKH; d++) {
            const float qd = Qs[warp][d];
            s0 += qd * Ks[lane * 65 + d];
            s1 += qd * Ks[(lane + 32) * 65 + d];
        }
        s0 = (lane      < nst) ? s0 * 0.125f : -1e30f;
        s1 = (lane + 32 < nst) ? s1 * 0.125f : -1e30f;

        const float m = wmax(fmaxf(fmaxf(s0, s1), sdiag));
        const float e0 = (lane      < nst) ? __expf(s0 - m) : 0.f;
        const float e1 = (lane + 32 < nst) ? __expf(s1 - m) : 0.f;
        const float ediag = __expf(sdiag - m);
        const float den = wsum(e0 + e1) + ediag;

        Ps[warp][lane]      = e0;
        Ps[warp][lane + 32] = e1;
        __syncwarp();

        const float* vrow = vb + (size_t)i * DM;
        float a0 = ediag * vrow[d0];
        float a1 = ediag * vrow[d0 + 1];
        #pragma unroll 8
        for (int t = 0; t < NSTR; t++) {
            const float p = Ps[warp][t];
            a0 += p * Vs[t * 65 + d0];
            a1 += p * Vs[t * 65 + d0 + 1];
        }
        const float inv = 1.0f / den;
        float* out = ctx + base + (size_t)i * DM;
        out[d0]     = a0 * inv;
        out[d0 + 1] = a1 * inv;
        __syncwarp();
    }
}

// ---------------------------------------------------------------------------
// Special rows (i = 32m): keys = {j%32==0, j<i} U {j>=i}. Online softmax.
// ---------------------------------------------------------------------------
__global__ __launch_bounds__(256) void attn_special(
    const float* __restrict__ q, const float* __restrict__ k,
    const float* __restrict__ v, float* __restrict__ ctx)
{
    const int bh = blockIdx.x;
    const int b = bh >> 4, h = bh & 15;
    const int warp = threadIdx.x >> 5, lane = threadIdx.x & 31;
    const int m = blockIdx.y * 8 + warp;
    const int i = m * STRIDE;
    const size_t base = (size_t)b * SS * DM + (size_t)h * DKH;

    const int d0 = 2 * lane;
    const float* qrow = q + base + (size_t)i * DM;
    const float q0 = qrow[d0], q1 = qrow[d0 + 1];
    const float* kb = k + base;
    const float* vb = v + base;

    float mx = -1e30f, den = 0.f, a0 = 0.f, a1 = 0.f;

    auto process = [&](int j) {
        const float2 kk = *(const float2*)(kb + (size_t)j * DM + d0);
        const float2 vv = *(const float2*)(vb + (size_t)j * DM + d0);
        float p = q0 * kk.x + q1 * kk.y;
        const float s = wsum(p) * 0.125f;
        const float mn = fmaxf(mx, s);
        const float c = __expf(mx - mn);
        const float e = __expf(s - mn);
        den = den * c + e;
        a0 = a0 * c + e * vv.x;
        a1 = a1 * c + e * vv.y;
        mx = mn;
    };

    for (int t = 0; t < m; t++) process(t * STRIDE);
    for (int j = i; j < SS; j++) process(j);

    const float inv = 1.0f / den;
    float* out = ctx + base + (size_t)i * DM;
    out[d0]     = a0 * inv;
    out[d0 + 1] = a1 * inv;
}

// ---------------------------------------------------------------------------
extern "C" void kernel_launch(void* const* d_in, const int* in_sizes, int n_in,
                              void* d_out, int out_size)
{
    const float* q_in = (const float*)d_in[0];
    const float* k_in = (const float*)d_in[1];
    const float* v_in = (const float*)d_in[2];
    const float* Wq = (const float*)d_in[3];
    const float* bq = (const float*)d_in[4];
    const float* Wk = (const float*)d_in[5];
    const float* bk = (const float*)d_in[6];
    const float* Wv = (const float*)d_in[7];
    const float* bv = (const float*)d_in[8];
    const float* Wo = (const float*)d_in[9];
    const float* bo = (const float*)d_in[10];

    float *pq, *pk, *pv, *pc;
    __nv_bfloat16 *ahi, *alo, *wthi, *wtlo;
    cudaGetSymbolAddress((void**)&pq, g_q);
    cudaGetSymbolAddress((void**)&pk, g_k);
    cudaGetSymbolAddress((void**)&pv, g_v);
    cudaGetSymbolAddress((void**)&pc, g_ctx);
    cudaGetSymbolAddress((void**)&ahi, g_ahi);
    cudaGetSymbolAddress((void**)&alo, g_alo);
    cudaGetSymbolAddress((void**)&wthi, g_wthi);
    cudaGetSymbolAddress((void**)&wtlo, g_wtlo);

    cudaFuncSetAttribute(gemm_mma, cudaFuncAttributeMaxDynamicSharedMemorySize, GEMM_SMEM);

    const int nAct = MROWS * DM;
    const dim3 gw(32, 32);
    const dim3 gg(DM / 128, MROWS / 128);   // (8, 32)
    const int cvBlocks = nAct / 4 / 256;

    // W transposes + hi/lo conversion (order: Wq, Wk, Wv, Wo)
    wtrans<<<gw, 256>>>(Wq, wthi + 0 * (size_t)DM * DM, wtlo + 0 * (size_t)DM * DM);
    wtrans<<<gw, 256>>>(Wk, wthi + 1 * (size_t)DM * DM, wtlo + 1 * (size_t)DM * DM);
    wtrans<<<gw, 256>>>(Wv, wthi + 2 * (size_t)DM * DM, wtlo + 2 * (size_t)DM * DM);
    wtrans<<<gw, 256>>>(Wo, wthi + 3 * (size_t)DM * DM, wtlo + 3 * (size_t)DM * DM);

    // Q projection
    convert_act<<<cvBlocks, 256>>>(q_in, ahi, alo, nAct);
    gemm_mma<<<gg, 256, GEMM_SMEM>>>(ahi, alo, wthi + 0 * (size_t)DM * DM, wtlo + 0 * (size_t)DM * DM, bq, pq);
    // K projection
    convert_act<<<cvBlocks, 256>>>(k_in, ahi, alo, nAct);
    gemm_mma<<<gg, 256, GEMM_SMEM>>>(ahi, alo, wthi + 1 * (size_t)DM * DM, wtlo + 1 * (size_t)DM * DM, bk, pk);
    // V projection
    convert_act<<<cvBlocks, 256>>>(v_in, ahi, alo, nAct);
    gemm_mma<<<gg, 256, GEMM_SMEM>>>(ahi, alo, wthi + 2 * (size_t)DM * DM, wtlo + 2 * (size_t)DM * DM, bv, pv);

    // Sparse attention
    attn_regular<<<dim3(BB * NH, SS / 64), 256>>>(pq, pk, pv, pc);
    attn_special<<<dim3(BB * NH, NSTR / 8), 256>>>(pq, pk, pv, pc);

    // Output projection
    convert_act<<<cvBlocks, 256>>>(pc, ahi, alo, nAct);
    gemm_mma<<<gg, 256, GEMM_SMEM>>>(ahi, alo, wthi + 3 * (size_t)DM * DM, wtlo + 3 * (size_t)DM * DM, bo, (float*)d_out);
}

// round 7
// speedup vs baseline: 1.7966x; 1.3096x over previous
#include <cuda_runtime.h>
#include <cuda_bf16.h>
#include <math.h>
#include <stdint.h>

// Problem constants
#define BB      2
#define SS      2048
#define DM      1024
#define NH      16
#define DKH     64
#define STRIDE  32
#define NSTR    64          // SS / STRIDE
#define MROWS   (BB*SS)     // 4096

// ---------------------------------------------------------------------------
// Scratch (allocation-free rule: __device__ globals)
// ---------------------------------------------------------------------------
__device__ float g_q[(size_t)MROWS * DM];
__device__ float g_k[(size_t)MROWS * DM];
__device__ float g_v[(size_t)MROWS * DM];
__device__ float g_ctx[(size_t)MROWS * DM];
__device__ __nv_bfloat16 g_wthi[(size_t)4 * DM * DM];
__device__ __nv_bfloat16 g_wtlo[(size_t)4 * DM * DM];

// ---------------------------------------------------------------------------
// Helpers
// ---------------------------------------------------------------------------
__device__ __forceinline__ uint32_t smem_u32(const void* p) {
    uint32_t a;
    asm("{ .reg .u64 t; cvta.to.shared.u64 t, %1; cvt.u32.u64 %0, t; }" : "=r"(a) : "l"(p));
    return a;
}

#define CP16(dst, src) \
    asm volatile("cp.async.cg.shared.global [%0], [%1], 16;" :: "r"(dst), "l"(src))

#define LDSM4(r, addr) \
    asm volatile("ldmatrix.sync.aligned.m8n8.x4.shared.b16 {%0,%1,%2,%3}, [%4];" \
        : "=r"((r)[0]), "=r"((r)[1]), "=r"((r)[2]), "=r"((r)[3]) : "r"(addr))

#define MMA16816(c, a, b) \
    asm volatile("mma.sync.aligned.m16n8k16.row.col.f32.bf16.bf16.f32 " \
        "{%0,%1,%2,%3}, {%4,%5,%6,%7}, {%8,%9}, {%0,%1,%2,%3};" \
        : "+f"((c)[0]), "+f"((c)[1]), "+f"((c)[2]), "+f"((c)[3]) \
        : "r"((a)[0]), "r"((a)[1]), "r"((a)[2]), "r"((a)[3]), "r"((b)[0]), "r"((b)[1]))

// fp32 x8 -> bf16 hi/lo packed as uint4 each
__device__ __forceinline__ void cvt8(const float4 a, const float4 b, uint4& hi, uint4& lo) {
    float xs[8] = {a.x, a.y, a.z, a.w, b.x, b.y, b.z, b.w};
    __nv_bfloat16 h[8], l[8];
    #pragma unroll
    for (int e = 0; e < 8; e++) {
        h[e] = __float2bfloat16(xs[e]);
        l[e] = __float2bfloat16(xs[e] - __bfloat162float(h[e]));
    }
    uint32_t* hp = (uint32_t*)&hi;
    uint32_t* lp = (uint32_t*)&lo;
    #pragma unroll
    for (int e = 0; e < 4; e++) {
        __nv_bfloat162 hh = {h[2*e], h[2*e+1]}, ll = {l[2*e], l[2*e+1]};
        hp[e] = *(uint32_t*)&hh;
        lp[e] = *(uint32_t*)&ll;
    }
}

// ---------------------------------------------------------------------------
// Transpose + convert: W[K=1024][N=1024] fp32 -> Wt_hi/Wt_lo [N][K] bf16
// ---------------------------------------------------------------------------
__global__ __launch_bounds__(256) void wtrans(
    const float* __restrict__ W, __nv_bfloat16* __restrict__ Thi,
    __nv_bfloat16* __restrict__ Tlo)
{
    __shared__ float tile[32][33];
    const int tx = threadIdx.x & 31, ty = threadIdx.x >> 5;
    const int n0 = blockIdx.x * 32, k0 = blockIdx.y * 32;
    #pragma unroll
    for (int i = 0; i < 32; i += 8)
        tile[ty + i][tx] = W[(size_t)(k0 + ty + i) * DM + n0 + tx];
    __syncthreads();
    #pragma unroll
    for (int i = 0; i < 32; i += 8) {
        float x = tile[tx][ty + i];
        __nv_bfloat16 h = __float2bfloat16(x);
        __nv_bfloat16 l = __float2bfloat16(x - __bfloat162float(h));
        Thi[(size_t)(n0 + ty + i) * DM + k0 + tx] = h;
        Tlo[(size_t)(n0 + ty + i) * DM + k0 + tx] = l;
    }
}

// ---------------------------------------------------------------------------
// mma.sync bf16 GEMM with fused fp32->hi/lo A conversion.
// C[4096,1024] = A_fp32 @ Wt^T + bias.  3-term hi/lo split.
// 128x128 CTA tile, BK=64, double-buffered (A: LDG+cvt+STS, B: cp.async).
// 8 warps 2(M)x4(N), warp tile 64x32, mma m16n8k16, SW128 swizzle.
// SMEM/stage (64KB): Ah(16K) Al(16K) Bh(16K) Bl(16K); 2 stages = 128KB.
// ---------------------------------------------------------------------------
#define TILE_B   16384
#define STAGE_B  65536
#define GEMM_SMEM (2 * STAGE_B)
#define NKB      (DM / 64)   // 16

__global__ __launch_bounds__(256, 1) void gemm_mma(
    const float* __restrict__ A,
    const __nv_bfloat16* __restrict__ Bhi, const __nv_bfloat16* __restrict__ Blo,
    const float* __restrict__ bias, float* __restrict__ C)
{
    extern __shared__ __align__(1024) char smem[];
    const uint32_t sbase = smem_u32(smem);
    const int tid = threadIdx.x, wid = tid >> 5, lane = tid & 31;
    const int n0 = blockIdx.x * 128;
    const int m0 = blockIdx.y * 128;
    const int wm = wid >> 2, wn = wid & 3;

    // Loader: thread t -> row t/2 (0..127), chunks (t&1)*4 .. +3 (8 elems each)
    const int lr = tid >> 1;
    const int lc = (tid & 1) * 4;
    const float* gA = A + (size_t)(m0 + lr) * DM;
    const __nv_bfloat16* gBh = Bhi + (size_t)(n0 + lr) * DM;
    const __nv_bfloat16* gBl = Blo + (size_t)(n0 + lr) * DM;

    auto load_stage = [&](int s, int kb) {
        const int k0 = kb * 64;
        const uint32_t sdst = sbase + s * STAGE_B;
        char* stg = smem + s * STAGE_B;
        #pragma unroll
        for (int j = 0; j < 4; j++) {
            const int chunk = lc + j;
            const uint32_t off = (uint32_t)(lr * 128 + chunk * 16);
            const uint32_t sw = off ^ ((off >> 3) & 0x70);
            float4 fa = *(const float4*)(gA + k0 + chunk * 8);
            float4 fb = *(const float4*)(gA + k0 + chunk * 8 + 4);
            uint4 hi, lo;
            cvt8(fa, fb, hi, lo);
            *(uint4*)(stg + 0 * TILE_B + sw) = hi;
            *(uint4*)(stg + 1 * TILE_B + sw) = lo;
            CP16(sdst + 2 * TILE_B + sw, gBh + k0 + chunk * 8);
            CP16(sdst + 3 * TILE_B + sw, gBl + k0 + chunk * 8);
        }
        asm volatile("cp.async.commit_group;" ::: "memory");
    };

    float acc[4][4][4];
    #pragma unroll
    for (int mt = 0; mt < 4; mt++)
        #pragma unroll
        for (int nt = 0; nt < 4; nt++)
            #pragma unroll
            for (int i = 0; i < 4; i++) acc[mt][nt][i] = 0.f;

    load_stage(0, 0);
    load_stage(1, 1);

    const int la = lane & 15;
    const int hb = (lane >> 4) * 16;

    for (int kb = 0; kb < NKB; kb++) {
        if (kb < NKB - 1) asm volatile("cp.async.wait_group 1;" ::: "memory");
        else              asm volatile("cp.async.wait_group 0;" ::: "memory");
        __syncthreads();

        const uint32_t sa = sbase + (kb & 1) * STAGE_B;
        #pragma unroll
        for (int kk = 0; kk < 4; kk++) {
            uint32_t ah[4][4], al[4][4], bh[4][2], bl[4][2];
            #pragma unroll
            for (int mt = 0; mt < 4; mt++) {
                const uint32_t off = (uint32_t)((64 * wm + 16 * mt + la) * 128 + 32 * kk + hb);
                const uint32_t sw = off ^ ((off >> 3) & 0x70);
                LDSM4(ah[mt], sa + 0 * TILE_B + sw);
                LDSM4(al[mt], sa + 1 * TILE_B + sw);
            }
            #pragma unroll
            for (int bp = 0; bp < 2; bp++) {
                const uint32_t off = (uint32_t)((32 * wn + 16 * bp + la) * 128 + 32 * kk + hb);
                const uint32_t sw = off ^ ((off >> 3) & 0x70);
                uint32_t t[4];
                LDSM4(t, sa + 2 * TILE_B + sw);
                bh[2 * bp][0] = t[0]; bh[2 * bp + 1][0] = t[1];
                bh[2 * bp][1] = t[2]; bh[2 * bp + 1][1] = t[3];
                LDSM4(t, sa + 3 * TILE_B + sw);
                bl[2 * bp][0] = t[0]; bl[2 * bp + 1][0] = t[1];
                bl[2 * bp][1] = t[2]; bl[2 * bp + 1][1] = t[3];
            }
            #pragma unroll
            for (int mt = 0; mt < 4; mt++)
                #pragma unroll
                for (int nt = 0; nt < 4; nt++) {
                    MMA16816(acc[mt][nt], ah[mt], bh[nt]);
                    MMA16816(acc[mt][nt], ah[mt], bl[nt]);
                    MMA16816(acc[mt][nt], al[mt], bh[nt]);
                }
        }
        __syncthreads();
        if (kb + 2 < NKB) load_stage(kb & 1, kb + 2);
    }

    const int er = lane >> 2, ec = (lane & 3) * 2;
    #pragma unroll
    for (int mt = 0; mt < 4; mt++) {
        const int row = m0 + 64 * wm + 16 * mt + er;
        #pragma unroll
        for (int nt = 0; nt < 4; nt++) {
            const int col = n0 + 32 * wn + 8 * nt + ec;
            const float2 b2 = *(const float2*)(bias + col);
            float2 o0, o1;
            o0.x = acc[mt][nt][0] + b2.x; o0.y = acc[mt][nt][1] + b2.y;
            o1.x = acc[mt][nt][2] + b2.x; o1.y = acc[mt][nt][3] + b2.y;
            *(float2*)(C + (size_t)row * DM + col) = o0;
            *(float2*)(C + (size_t)(row + 8) * DM + col) = o1;
        }
    }
}

// ---------------------------------------------------------------------------
// Warp reductions
// ---------------------------------------------------------------------------
__device__ __forceinline__ float wsum(float v) {
    #pragma unroll
    for (int o = 16; o > 0; o >>= 1) v += __shfl_xor_sync(0xffffffffu, v, o);
    return v;
}
__device__ __forceinline__ float wmax(float v) {
    #pragma unroll
    for (int o = 16; o > 0; o >>= 1) v = fmaxf(v, __shfl_xor_sync(0xffffffffu, v, o));
    return v;
}

// ---------------------------------------------------------------------------
// Regular rows (i % 32 != 0): keys = {j%32==0, j<=i} (<=64) + diagonal.
// ---------------------------------------------------------------------------
__global__ __launch_bounds__(256) void attn_regular(
    const float* __restrict__ q, const float* __restrict__ k,
    const float* __restrict__ v, float* __restrict__ ctx)
{
    __shared__ float Ks[NSTR * 65];
    __shared__ float Vs[NSTR * 65];
    __shared__ float Qs[8][64];
    __shared__ float Ps[8][64];

    const int bh = blockIdx.x;
    const int b = bh >> 4, h = bh & 15;
    const int tid = threadIdx.x, warp = tid >> 5, lane = tid & 31;
    const size_t base = (size_t)b * SS * DM + (size_t)h * DKH;

    const float* kb = k + base;
    const float* vb = v + base;

    for (int idx = tid; idx < NSTR * DKH; idx += 256) {
        const int t = idx >> 6, d = idx & 63;
        const size_t off = (size_t)(t * STRIDE) * DM + d;
        Ks[t * 65 + d] = kb[off];
        Vs[t * 65 + d] = vb[off];
    }
    __syncthreads();

    const int irow0 = blockIdx.y * 64 + warp * 8;
    for (int qi = 0; qi < 8; qi++) {
        const int i = irow0 + qi;
        if ((i & (STRIDE - 1)) == 0) continue;

        const float* qrow = q + base + (size_t)i * DM;
        Qs[warp][lane]      = qrow[lane];
        Qs[warp][lane + 32] = qrow[lane + 32];
        __syncwarp();

        const int nst = i / STRIDE + 1;

        const float* krow = kb + (size_t)i * DM;
        const int d0 = 2 * lane;
        float dp = Qs[warp][d0] * krow[d0] + Qs[warp][d0 + 1] * krow[d0 + 1];
        const float sdiag = wsum(dp) * 0.125f;

        float s0 = 0.f, s1 = 0.f;
        #pragma unroll 8
        for (int d = 0; d < DKH; d++) {
            const float qd = Qs[warp][d];
            s0 += qd * Ks[lane * 65 + d];
            s1 += qd * Ks[(lane + 32) * 65 + d];
        }
        s0 = (lane      < nst) ? s0 * 0.125f : -1e30f;
        s1 = (lane + 32 < nst) ? s1 * 0.125f : -1e30f;

        const float m = wmax(fmaxf(fmaxf(s0, s1), sdiag));
        const float e0 = (lane      < nst) ? __expf(s0 - m) : 0.f;
        const float e1 = (lane + 32 < nst) ? __expf(s1 - m) : 0.f;
        const float ediag = __expf(sdiag - m);
        const float den = wsum(e0 + e1) + ediag;

        Ps[warp][lane]      = e0;
        Ps[warp][lane + 32] = e1;
        __syncwarp();

        const float* vrow = vb + (size_t)i * DM;
        float a0 = ediag * vrow[d0];
        float a1 = ediag * vrow[d0 + 1];
        #pragma unroll 8
        for (int t = 0; t < NSTR; t++) {
            const float p = Ps[warp][t];
            a0 += p * Vs[t * 65 + d0];
            a1 += p * Vs[t * 65 + d0 + 1];
        }
        const float inv = 1.0f / den;
        float* out = ctx + base + (size_t)i * DM;
        out[d0]     = a0 * inv;
        out[d0 + 1] = a1 * inv;
        __syncwarp();
    }
}

// ---------------------------------------------------------------------------
// Special rows (i = 32m): keys = {j%32==0, j<i} U {j>=i}.
// Block per (bh, m), 8-warp split-K online softmax + smem LSE merge.
// Dense segment unrolled x4 with interleaved shuffle reductions for ILP.
// ---------------------------------------------------------------------------
__global__ __launch_bounds__(256) void attn_special(
    const float* __restrict__ q, const float* __restrict__ k,
    const float* __restrict__ v, float* __restrict__ ctx)
{
    __shared__ float s_mx[8], s_den[8], s_a[8][64];

    const int bh = blockIdx.x;              // 0..31
    const int m  = blockIdx.y;              // 0..63
    const int b = bh >> 4, h = bh & 15;
    const int i = m * STRIDE;
    const int tid = threadIdx.x, w = tid >> 5, lane = tid & 31;
    const size_t base = (size_t)b * SS * DM + (size_t)h * DKH;

    const int d0 = 2 * lane;
    const float* qrow = q + base + (size_t)i * DM;
    const float q0 = qrow[d0], q1 = qrow[d0 + 1];
    const float* kp = k + base;
    const float* vp = v + base;

    float mx = -1e30f, den = 0.f, a0 = 0.f, a1 = 0.f;

    auto upd = [&](float s, float2 vv) {
        const float mn = fmaxf(mx, s);
        const float c = __expf(mx - mn);
        const float e = __expf(s - mn);
        den = den * c + e;
        a0 = a0 * c + e * vv.x;
        a1 = a1 * c + e * vv.y;
        mx = mn;
    };

    // Strided prefix: keys j = 32t, t = w, w+8, ... < m
    for (int t = w; t < m; t += 8) {
        const size_t ro = (size_t)(t * STRIDE) * DM + d0;
        const float2 kk = *(const float2*)(kp + ro);
        const float2 vv = *(const float2*)(vp + ro);
        float p = q0 * kk.x + q1 * kk.y;
        #pragma unroll
        for (int o = 16; o > 0; o >>= 1) p += __shfl_xor_sync(0xffffffffu, p, o);
        upd(p * 0.125f, vv);
    }

    // Dense suffix: warp w takes j = i + w + 8u; count per warp = 256-4m (div by 4)
    for (int j0 = i + w; j0 < SS; j0 += 32) {
        float p[4];
        float2 vv[4];
        #pragma unroll
        for (int u = 0; u < 4; u++) {
            const size_t ro = (size_t)(j0 + 8 * u) * DM + d0;
            const float2 kk = *(const float2*)(kp + ro);
            vv[u] = *(const float2*)(vp + ro);
            p[u] = q0 * kk.x + q1 * kk.y;
        }
        #pragma unroll
        for (int o = 16; o > 0; o >>= 1) {
            p[0] += __shfl_xor_sync(0xffffffffu, p[0], o);
            p[1] += __shfl_xor_sync(0xffffffffu, p[1], o);
            p[2] += __shfl_xor_sync(0xffffffffu, p[2], o);
            p[3] += __shfl_xor_sync(0xffffffffu, p[3], o);
        }
        upd(p[0] * 0.125f, vv[0]);
        upd(p[1] * 0.125f, vv[1]);
        upd(p[2] * 0.125f, vv[2]);
        upd(p[3] * 0.125f, vv[3]);
    }

    // Publish warp partials
    s_a[w][d0]     = a0;
    s_a[w][d0 + 1] = a1;
    if (lane == 0) { s_mx[w] = mx; s_den[w] = den; }
    __syncthreads();

    // Merge 8 partials (threads 0..63, one dim each)
    if (tid < 64) {
        float M = s_mx[0];
        #pragma unroll
        for (int ww = 1; ww < 8; ww++) M = fmaxf(M, s_mx[ww]);
        float D = 0.f, val = 0.f;
        #pragma unroll
        for (int ww = 0; ww < 8; ww++) {
            const float f = __expf(s_mx[ww] - M);
            D   += s_den[ww] * f;
            val += s_a[ww][tid] * f;
        }
        ctx[base + (size_t)i * DM + tid] = val / D;
    }
}

// ---------------------------------------------------------------------------
extern "C" void kernel_launch(void* const* d_in, const int* in_sizes, int n_in,
                              void* d_out, int out_size)
{
    const float* q_in = (const float*)d_in[0];
    const float* k_in = (const float*)d_in[1];
    const float* v_in = (const float*)d_in[2];
    const float* Wq = (const float*)d_in[3];
    const float* bq = (const float*)d_in[4];
    const float* Wk = (const float*)d_in[5];
    const float* bk = (const float*)d_in[6];
    const float* Wv = (const float*)d_in[7];
    const float* bv = (const float*)d_in[8];
    const float* Wo = (const float*)d_in[9];
    const float* bo = (const float*)d_in[10];

    float *pq, *pk, *pv, *pc;
    __nv_bfloat16 *wthi, *wtlo;
    cudaGetSymbolAddress((void**)&pq, g_q);
    cudaGetSymbolAddress((void**)&pk, g_k);
    cudaGetSymbolAddress((void**)&pv, g_v);
    cudaGetSymbolAddress((void**)&pc, g_ctx);
    cudaGetSymbolAddress((void**)&wthi, g_wthi);
    cudaGetSymbolAddress((void**)&wtlo, g_wtlo);

    cudaFuncSetAttribute(gemm_mma, cudaFuncAttributeMaxDynamicSharedMemorySize, GEMM_SMEM);

    const dim3 gw(32, 32);
    const dim3 gg(DM / 128, MROWS / 128);   // (8, 32)

    // W transposes + hi/lo conversion (order: Wq, Wk, Wv, Wo)
    wtrans<<<gw, 256>>>(Wq, wthi + 0 * (size_t)DM * DM, wtlo + 0 * (size_t)DM * DM);
    wtrans<<<gw, 256>>>(Wk, wthi + 1 * (size_t)DM * DM, wtlo + 1 * (size_t)DM * DM);
    wtrans<<<gw, 256>>>(Wv, wthi + 2 * (size_t)DM * DM, wtlo + 2 * (size_t)DM * DM);
    wtrans<<<gw, 256>>>(Wo, wthi + 3 * (size_t)DM * DM, wtlo + 3 * (size_t)DM * DM);

    // Projections (fused fp32->hi/lo conversion inside the GEMM)
    gemm_mma<<<gg, 256, GEMM_SMEM>>>(q_in, wthi + 0 * (size_t)DM * DM, wtlo + 0 * (size_t)DM * DM, bq, pq);
    gemm_mma<<<gg, 256, GEMM_SMEM>>>(k_in, wthi + 1 * (size_t)DM * DM, wtlo + 1 * (size_t)DM * DM, bk, pk);
    gemm_mma<<<gg, 256, GEMM_SMEM>>>(v_in, wthi + 2 * (size_t)DM * DM, wtlo + 2 * (size_t)DM * DM, bv, pv);

    // Sparse attention
    attn_regular<<<dim3(BB * NH, SS / 64), 256>>>(pq, pk, pv, pc);
    attn_special<<<dim3(BB * NH, NSTR), 256>>>(pq, pk, pv, pc);

    // Output projection
    gemm_mma<<<gg, 256, GEMM_SMEM>>>(pc, wthi + 3 * (size_t)DM * DM, wtlo + 3 * (size_t)DM * DM, bo, (float*)d_out);
}